// round 14
// baseline (speedup 1.0000x reference)
#include <cuda_runtime.h>
#include <cuda_fp16.h>
#include <cstdint>
#include <math.h>
#include <float.h>

// Problem constants
#define BB  8
#define SS  1024
#define EE  512
#define HH  8
#define DD  64
#define FFD 2048
#define LLAYERS 4
#define MTOT (BB*SS)     // 8192 rows
#define QKVN 1536
#define QKVLD 1536

// ---------------- scratch (static device globals; no allocations) -----------
__device__ float  g_x   [BB*SS*EE];          // residual stream (fp32)
__device__ __half g_h   [BB*SS*EE];
__device__ __half g_qkv [BB*SS*QKVN];        // fused Q|K|V output
__device__ __half g_vT  [BB*HH*DD*SS];
__device__ __half g_attn[BB*SS*EE];
__device__ __half g_ffn [BB*SS*FFD];
__device__ float  g_bqkv[LLAYERS*QKVN];      // concat bias
// transposed weights [N,K] K-major, fp16
__device__ __half g_wqkvT[LLAYERS*QKVN*EE];
__device__ __half g_woT[LLAYERS*EE*EE];
__device__ __half g_w1T[LLAYERS*FFD*EE];
__device__ __half g_w2T[LLAYERS*EE*FFD];

// ---------------- helpers ---------------------------------------------------
__device__ __forceinline__ uint32_t smem_u32(const void* p) {
    uint32_t a;
    asm("{ .reg .u64 t; cvta.to.shared.u64 t, %1; cvt.u32.u64 %0, t; }" : "=r"(a) : "l"(p));
    return a;
}
#define CP_ASYNC16(dst, src) \
    asm volatile("cp.async.ca.shared.global [%0], [%1], 16;" :: "r"(dst), "l"(src))
#define CP_COMMIT() asm volatile("cp.async.commit_group;" ::: "memory")
#define CP_WAIT1()  asm volatile("cp.async.wait_group 1;" ::: "memory")
#define CP_WAIT0()  asm volatile("cp.async.wait_group 0;" ::: "memory")
#define LDSM4(r0, r1, r2, r3, addr) \
    asm volatile("ldmatrix.sync.aligned.m8n8.x4.shared.b16 {%0,%1,%2,%3}, [%4];" \
        : "=r"(r0), "=r"(r1), "=r"(r2), "=r"(r3) : "r"(addr))
#define MMA_F16(acc, a, b) \
    asm volatile("mma.sync.aligned.m16n8k16.row.col.f32.f16.f16.f32 " \
        "{%0,%1,%2,%3}, {%4,%5,%6,%7}, {%8,%9}, {%0,%1,%2,%3};" \
        : "+f"((acc)[0]), "+f"((acc)[1]), "+f"((acc)[2]), "+f"((acc)[3]) \
        : "r"((a)[0]), "r"((a)[1]), "r"((a)[2]), "r"((a)[3]), "r"((b)[0]), "r"((b)[1]))

// ---------------- fp16 mma GEMM, 3-stage pipeline -----------------------------
// C[M,N] = epi( A[M,K] @ B[N,K]^T ).  BM=128, BN=128, BK=64 halves.
// 256 threads = 8 warps (4x2), warp tile 32x64. One __syncthreads per chunk.
// EPI: 0 +bias -> half out, 1 gelu(+bias) -> half out, 2 +bias+res -> float out
#define PADH 72
template<int EPI, int BN>
__global__ void __launch_bounds__(256)
mma_gemm(const __half* __restrict__ A, int lda,
         const __half* __restrict__ Bm, int ldb,
         void* __restrict__ Cv, int ldc,
         const float* __restrict__ bias, const float* __restrict__ res,
         int M, int N, int K)
{
    constexpr int BM = 128, WN = BN / 2, NI = WN / 8;

    extern __shared__ __half smh[];
    __half* Asm = smh;                       // [3][BM*PADH]
    __half* Bsm = smh + 3 * BM * PADH;       // [3][BN*PADH]
    const uint32_t sbA = smem_u32(Asm), sbB = smem_u32(Bsm);

    const int tid = threadIdx.x, warp = tid >> 5, lane = tid & 31;
    const int g = lane >> 2, tg = lane & 3;
    const int wr = warp & 3, wc = warp >> 2;
    const int m0 = blockIdx.y * BM, n0 = blockIdx.x * BN;

    const int arow = wr * 32 + ((lane >> 3) & 1) * 8 + (lane & 7);
    const int acol = ((lane >> 4) & 1) * 8;
    const int brow = ((lane >> 4) & 1) * 8 + (lane & 7);
    const int bcol = ((lane >> 3) & 1) * 8;

    float acc[2][NI][4];
#pragma unroll
    for (int mi = 0; mi < 2; mi++)
#pragma unroll
        for (int ni = 0; ni < NI; ni++)
#pragma unroll
            for (int j = 0; j < 4; j++) acc[mi][ni][j] = 0.f;

    auto load_chunk = [&](int c, int buf) {
        const __half* Ab = A + (size_t)m0 * lda + c * 64;
#pragma unroll
        for (int i = 0; i < 4; i++) {
            int e = i * 256 + tid, row = e >> 3, c8 = e & 7;
            CP_ASYNC16(sbA + (uint32_t)(((buf * BM + row) * PADH + c8 * 8) * 2),
                       Ab + (size_t)row * lda + c8 * 8);
        }
        const __half* Bb = Bm + (size_t)n0 * ldb + c * 64;
#pragma unroll
        for (int i = 0; i < BN / 32; i++) {
            int e = i * 256 + tid, row = e >> 3, c8 = e & 7;
            CP_ASYNC16(sbB + (uint32_t)(((buf * BN + row) * PADH + c8 * 8) * 2),
                       Bb + (size_t)row * ldb + c8 * 8);
        }
        CP_COMMIT();
    };

    auto compute = [&](int buf) {
        const uint32_t baA = sbA + (uint32_t)(buf * BM * PADH * 2);
        const uint32_t baB = sbB + (uint32_t)(buf * BN * PADH * 2);
#pragma unroll
        for (int ks = 0; ks < 4; ks++) {
            const int k0 = ks * 16;
            uint32_t af[2][4];
#pragma unroll
            for (int mi = 0; mi < 2; mi++)
                LDSM4(af[mi][0], af[mi][1], af[mi][2], af[mi][3],
                      baA + (uint32_t)(((arow + mi * 16) * PADH + k0 + acol) * 2));
            uint32_t bf[NI][2];
#pragma unroll
            for (int p = 0; p < NI / 2; p++) {
                uint32_t r0, r1, r2, r3;
                LDSM4(r0, r1, r2, r3,
                      baB + (uint32_t)(((wc * WN + brow + p * 16) * PADH + k0 + bcol) * 2));
                bf[2*p][0] = r0; bf[2*p][1] = r1;
                bf[2*p+1][0] = r2; bf[2*p+1][1] = r3;
            }
#pragma unroll
            for (int mi = 0; mi < 2; mi++)
#pragma unroll
                for (int ni = 0; ni < NI; ni++)
                    MMA_F16(acc[mi][ni], af[mi], bf[ni]);
        }
    };

    const int nch = K >> 6;
    load_chunk(0, 0);
    if (nch > 1) load_chunk(1, 1);
    int bufc = 0;
    for (int c = 0; c < nch; ++c) {
        if (c + 1 < nch) { CP_WAIT1(); } else { CP_WAIT0(); }
        __syncthreads();                   // all warps done with compute(c-1)
        if (c + 2 < nch) {
            int bn = bufc + 2; if (bn >= 3) bn -= 3;
            load_chunk(c + 2, bn);
        }
        compute(bufc);
        if (++bufc == 3) bufc = 0;
    }

#pragma unroll
    for (int mi = 0; mi < 2; mi++)
#pragma unroll
        for (int ni = 0; ni < NI; ni++)
#pragma unroll
            for (int hh = 0; hh < 2; hh++) {
                const int r   = m0 + wr * 32 + mi * 16 + g + hh * 8;
                const int col = n0 + wc * WN + ni * 8 + tg * 2;
                float vx = acc[mi][ni][hh * 2], vy = acc[mi][ni][hh * 2 + 1];
                float2 bb = *(const float2*)(bias + col);
                vx += bb.x; vy += bb.y;
                if (EPI == 1) {
                    vx = 0.5f * vx * (1.f + erff(vx * 0.70710678118654752f));
                    vy = 0.5f * vy * (1.f + erff(vy * 0.70710678118654752f));
                }
                if (EPI == 2) {
                    float2 rr = *(const float2*)(res + (size_t)r * ldc + col);
                    *(float2*)((float*)Cv + (size_t)r * ldc + col) =
                        make_float2(vx + rr.x, vy + rr.y);
                } else {
                    *(__half2*)((__half*)Cv + (size_t)r * ldc + col) =
                        __floats2half2_rn(vx, vy);
                }
            }
}

// ---------------- fused flash attention (R7 smem-P design + KV double buffer) -
#define PVH 136   // V/P row stride in halves
#define PSF 132   // S row stride in floats
// smem layout in halves:
#define FQ_K  (128*PADH)                  // after Q: 2 K buffers
#define FQ_V  (FQ_K + 2*128*PADH)         // 2 V buffers
#define FQ_P  (FQ_V + 2*64*PVH)           // P (fp16)
#define FQ_F  (FQ_P + 128*PVH)            // float region start (in halves)
__global__ void __launch_bounds__(256)
flash_k(const __half* __restrict__ qkv, const __half* __restrict__ vt,
        __half* __restrict__ o,
        const float* __restrict__ edge, const unsigned char* __restrict__ mask)
{
    extern __shared__ __half smh[];
    float* Ssm  = (float*)(smh + FQ_F);   // 128*132
    float* mrow = Ssm + 128 * PSF;
    float* lrow = mrow + 128;
    float* rowf = lrow + 128;

    const int tid = threadIdx.x, warp = tid >> 5, lane = tid & 31;
    const int g = lane >> 2, tg = lane & 3;
    const int wr = warp & 3, wc = warp >> 2;
    const int t0 = blockIdx.x * 128;
    const int bh = blockIdx.y, b = bh >> 3, h = bh & 7;

    const __half* Qg = qkv + ((size_t)b * SS + t0) * QKVLD + h * DD;
    const __half* Kg = qkv + (size_t)b * SS * QKVLD + EE + h * DD;
    const __half* Vg = vt + (size_t)bh * DD * SS;
    const uint32_t sQ = smem_u32(smh);
    const uint32_t sP = sQ + (uint32_t)(FQ_P * 2);

    // Q tile (128 x 64 halves) — commit group
#pragma unroll
    for (int i = 0; i < 4; i++) {
        int e = i * 256 + tid, row = e >> 3, c8 = e & 7;
        CP_ASYNC16(sQ + (uint32_t)((row * PADH + c8 * 8) * 2), Qg + (size_t)row * QKVLD + c8 * 8);
    }
    CP_COMMIT();

    auto load_kv = [&](int kt, int buf) {
        const int s0 = kt * 128;
        const uint32_t sK = sQ + (uint32_t)((FQ_K + buf * 128 * PADH) * 2);
        const uint32_t sV = sQ + (uint32_t)((FQ_V + buf * 64 * PVH) * 2);
#pragma unroll
        for (int i = 0; i < 4; i++) {
            int e = i * 256 + tid, row = e >> 3, c8 = e & 7;
            CP_ASYNC16(sK + (uint32_t)((row * PADH + c8 * 8) * 2),
                       Kg + (size_t)(s0 + row) * QKVLD + c8 * 8);
        }
#pragma unroll
        for (int i = 0; i < 4; i++) {
            int e = i * 256 + tid, row = e >> 4, c8 = e & 15;
            CP_ASYNC16(sV + (uint32_t)((row * PVH + c8 * 8) * 2),
                       Vg + (size_t)row * SS + s0 + c8 * 8);
        }
        CP_COMMIT();
    };
    load_kv(0, 0);

    if (tid < 128) { mrow[tid] = -FLT_MAX; lrow[tid] = 0.f; }

    float acco[2][4][4];
#pragma unroll
    for (int mi = 0; mi < 2; mi++)
#pragma unroll
        for (int ni = 0; ni < 4; ni++)
#pragma unroll
            for (int j = 0; j < 4; j++) acco[mi][ni][j] = 0.f;

    const int arow = wr * 32 + ((lane >> 3) & 1) * 8 + (lane & 7);
    const int acol = ((lane >> 4) & 1) * 8;
    const int brow = ((lane >> 4) & 1) * 8 + (lane & 7);
    const int bcol = ((lane >> 3) & 1) * 8;

    for (int kt = 0; kt < 8; kt++) {
        const int s0 = kt * 128;
        const int buf = kt & 1;
        if (kt < 7) { load_kv(kt + 1, buf ^ 1); CP_WAIT1(); }
        else        { CP_WAIT0(); }
        __syncthreads();
        const uint32_t sK = sQ + (uint32_t)((FQ_K + buf * 128 * PADH) * 2);
        const uint32_t sV = sQ + (uint32_t)((FQ_V + buf * 64 * PVH) * 2);

        // S = Q @ K^T (128x128), warp tile 32x64
        float accs[2][8][4];
#pragma unroll
        for (int mi = 0; mi < 2; mi++)
#pragma unroll
            for (int ni = 0; ni < 8; ni++)
#pragma unroll
                for (int j = 0; j < 4; j++) accs[mi][ni][j] = 0.f;
#pragma unroll
        for (int ks = 0; ks < 4; ks++) {
            const int k0 = ks * 16;
            uint32_t af[2][4];
#pragma unroll
            for (int mi = 0; mi < 2; mi++)
                LDSM4(af[mi][0], af[mi][1], af[mi][2], af[mi][3],
                      sQ + (uint32_t)(((arow + mi * 16) * PADH + k0 + acol) * 2));
            uint32_t bf[8][2];
#pragma unroll
            for (int p = 0; p < 4; p++) {
                uint32_t r0, r1, r2, r3;
                LDSM4(r0, r1, r2, r3,
                      sK + (uint32_t)(((wc * 64 + brow + p * 16) * PADH + k0 + bcol) * 2));
                bf[2*p][0] = r0; bf[2*p][1] = r1;
                bf[2*p+1][0] = r2; bf[2*p+1][1] = r3;
            }
#pragma unroll
            for (int mi = 0; mi < 2; mi++)
#pragma unroll
                for (int ni = 0; ni < 8; ni++)
                    MMA_F16(accs[mi][ni], af[mi], bf[ni]);
        }

        // scale + mask + edge -> Ssm (fp32)
#pragma unroll
        for (int mi = 0; mi < 2; mi++)
#pragma unroll
            for (int ni = 0; ni < 8; ni++)
#pragma unroll
                for (int hh = 0; hh < 2; hh++) {
                    const int r  = wr * 32 + mi * 16 + g + hh * 8;
                    const int cc = wc * 64 + ni * 8 + tg * 2;
                    float2 ee = *(const float2*)(edge + ((size_t)b * SS + t0 + r) * SS + s0 + cc);
                    const unsigned char* Mp = mask + (size_t)b * SS + s0 + cc;
                    Ssm[r * PSF + cc]     = (Mp[0] ? -FLT_MAX : accs[mi][ni][hh*2]     * 0.125f) + ee.x;
                    Ssm[r * PSF + cc + 1] = (Mp[1] ? -FLT_MAX : accs[mi][ni][hh*2 + 1] * 0.125f) + ee.y;
                }
        __syncthreads();

        // online softmax: 2 threads per row; write P as fp16
        {
            const int r = tid >> 1, hf = tid & 1;
            const float* Sr = Ssm + r * PSF + hf * 64;
            __half* Pr = (__half*)(smh + FQ_P) + r * PVH + hf * 64;
            float mloc = -FLT_MAX;
#pragma unroll
            for (int j = 0; j < 64; j += 4) {
                float4 v4 = *(const float4*)(Sr + j);
                mloc = fmaxf(mloc, fmaxf(fmaxf(v4.x, v4.y), fmaxf(v4.z, v4.w)));
            }
            mloc = fmaxf(mloc, __shfl_xor_sync(0xffffffffu, mloc, 1));
            const float mold = mrow[r];
            const float mnew = fmaxf(mold, mloc);
            const float f = __expf(mold - mnew);
            float sum = 0.f;
#pragma unroll
            for (int j = 0; j < 64; j += 4) {
                float4 v4 = *(const float4*)(Sr + j);
                v4.x = __expf(v4.x - mnew); v4.y = __expf(v4.y - mnew);
                v4.z = __expf(v4.z - mnew); v4.w = __expf(v4.w - mnew);
                sum += v4.x + v4.y + v4.z + v4.w;
                *(__half2*)(Pr + j)     = __floats2half2_rn(v4.x, v4.y);
                *(__half2*)(Pr + j + 2) = __floats2half2_rn(v4.z, v4.w);
            }
            sum += __shfl_xor_sync(0xffffffffu, sum, 1);
            if (hf == 0) { mrow[r] = mnew; rowf[r] = f; lrow[r] = lrow[r] * f + sum; }
        }
        __syncthreads();

        // rescale O accumulators
#pragma unroll
        for (int mi = 0; mi < 2; mi++)
#pragma unroll
            for (int hh = 0; hh < 2; hh++) {
                const int r = wr * 32 + mi * 16 + g + hh * 8;
                const float f = rowf[r];
#pragma unroll
                for (int ni = 0; ni < 4; ni++) {
                    acco[mi][ni][hh*2]     *= f;
                    acco[mi][ni][hh*2 + 1] *= f;
                }
            }

        // O += P @ V : warp tile 32x32, 8 k16 steps over the 128 s-dim
#pragma unroll
        for (int ks = 0; ks < 8; ks++) {
            const int k0 = ks * 16;
            uint32_t af[2][4];
#pragma unroll
            for (int mi = 0; mi < 2; mi++)
                LDSM4(af[mi][0], af[mi][1], af[mi][2], af[mi][3],
                      sP + (uint32_t)(((arow + mi * 16) * PVH + k0 + acol) * 2));
            uint32_t bf[4][2];
#pragma unroll
            for (int p = 0; p < 2; p++) {
                uint32_t r0, r1, r2, r3;
                LDSM4(r0, r1, r2, r3,
                      sV + (uint32_t)(((wc * 32 + brow + p * 16) * PVH + k0 + bcol) * 2));
                bf[2*p][0] = r0; bf[2*p][1] = r1;
                bf[2*p+1][0] = r2; bf[2*p+1][1] = r3;
            }
#pragma unroll
            for (int mi = 0; mi < 2; mi++)
#pragma unroll
                for (int ni = 0; ni < 4; ni++)
                    MMA_F16(acco[mi][ni], af[mi], bf[ni]);
        }
        __syncthreads();   // protect K/V/P buffers for next iteration
    }

    // write O = acc / l  (fp16, feeds Wo GEMM)
#pragma unroll
    for (int mi = 0; mi < 2; mi++)
#pragma unroll
        for (int ni = 0; ni < 4; ni++)
#pragma unroll
            for (int hh = 0; hh < 2; hh++) {
                const int r = wr * 32 + mi * 16 + g + hh * 8;
                const int d = wc * 32 + ni * 8 + tg * 2;
                const float inv = 1.f / lrow[r];
                *(__half2*)(o + ((size_t)b * SS + t0 + r) * EE + h * DD + d) =
                    __floats2half2_rn(acco[mi][ni][hh*2] * inv, acco[mi][ni][hh*2+1] * inv);
            }
}

// ---------------- weight transpose fp32 -> fp16 (with output placement) ------
__global__ void transpose_s(const float* __restrict__ in, __half* __restrict__ out,
                            int R, int Ccols, long long outLayerStride, int outRowOfs)
{
    in  += (size_t)blockIdx.z * R * Ccols;
    out += (size_t)blockIdx.z * outLayerStride + (size_t)outRowOfs * R;
    __shared__ float t[32][33];
    const int c0 = blockIdx.x * 32, r0 = blockIdx.y * 32;
    const int x = threadIdx.x, y = threadIdx.y;
#pragma unroll
    for (int i = 0; i < 32; i += 8)
        t[y + i][x] = in[(size_t)(r0 + y + i) * Ccols + c0 + x];
    __syncthreads();
#pragma unroll
    for (int i = 0; i < 32; i += 8)
        out[(size_t)(c0 + y + i) * R + r0 + x] = __float2half_rn(t[x][y + i]);
}

// ---------------- V transpose (half -> half), V lives in qkv at col 1024 -----
__global__ void vtrans_k(const __half* __restrict__ qkv, __half* __restrict__ vT)
{
    const int z = blockIdx.z, b = z >> 3, h = z & 7;
    const __half* in = qkv + (size_t)b * SS * QKVLD + 2 * EE + h * DD;
    __half* out = vT + (size_t)z * DD * SS;
    __shared__ __half t[32][36];
    const int d0 = blockIdx.x * 32, s0 = blockIdx.y * 32;
    const int x = threadIdx.x, y = threadIdx.y;
#pragma unroll
    for (int i = 0; i < 32; i += 8)
        t[y + i][x] = in[(size_t)(s0 + y + i) * QKVLD + d0 + x];
    __syncthreads();
#pragma unroll
    for (int i = 0; i < 32; i += 8)
        out[(size_t)(d0 + y + i) * SS + s0 + x] = t[x][y + i];
}

// ---------------- layernorm (fp32 in -> fp16 out) ----------------------------
__global__ __launch_bounds__(128)
void ln_k(const float* __restrict__ x, const float* __restrict__ g,
          const float* __restrict__ b, __half* __restrict__ o)
{
    const size_t row = blockIdx.x;
    const int tid = threadIdx.x;
    __shared__ float sma[4], smb[4];

    float4 v = ((const float4*)(x + row * EE))[tid];
    float s = v.x + v.y + v.z + v.w;
#pragma unroll
    for (int off = 16; off > 0; off >>= 1) s += __shfl_xor_sync(0xffffffffu, s, off);
    if ((tid & 31) == 0) sma[tid >> 5] = s;
    __syncthreads();
    const float mu = (sma[0] + sma[1] + sma[2] + sma[3]) * (1.f / EE);

    float4 d = make_float4(v.x - mu, v.y - mu, v.z - mu, v.w - mu);
    float s2 = d.x*d.x + d.y*d.y + d.z*d.z + d.w*d.w;
#pragma unroll
    for (int off = 16; off > 0; off >>= 1) s2 += __shfl_xor_sync(0xffffffffu, s2, off);
    if ((tid & 31) == 0) smb[tid >> 5] = s2;
    __syncthreads();
    const float var = (smb[0] + smb[1] + smb[2] + smb[3]) * (1.f / EE);
    const float rstd = rsqrtf(var + 1e-5f);

    float4 gg = ((const float4*)g)[tid];
    float4 bb = ((const float4*)b)[tid];
    __half2* op = (__half2*)(o + row * EE);
    op[tid * 2]     = __floats2half2_rn(d.x*rstd*gg.x + bb.x, d.y*rstd*gg.y + bb.y);
    op[tid * 2 + 1] = __floats2half2_rn(d.z*rstd*gg.z + bb.z, d.w*rstd*gg.w + bb.w);
}

// ---------------- host orchestration ----------------------------------------
extern "C" void kernel_launch(void* const* d_in, const int* in_sizes, int n_in,
                              void* d_out, int out_size)
{
    const float* src  = (const float*)d_in[0];
    const float* edge = (const float*)d_in[1];
    const unsigned char* mask = (const unsigned char*)d_in[2];
    const float* Wq = (const float*)d_in[3];
    const float* bq = (const float*)d_in[4];
    const float* Wk = (const float*)d_in[5];
    const float* bk = (const float*)d_in[6];
    const float* Wv = (const float*)d_in[7];
    const float* bvv = (const float*)d_in[8];
    const float* Wo = (const float*)d_in[9];
    const float* bo = (const float*)d_in[10];
    const float* ln1g = (const float*)d_in[11];
    const float* ln1b = (const float*)d_in[12];
    const float* ln2g = (const float*)d_in[13];
    const float* ln2b = (const float*)d_in[14];
    const float* W1 = (const float*)d_in[15];
    const float* b1 = (const float*)d_in[16];
    const float* W2 = (const float*)d_in[17];
    const float* b2 = (const float*)d_in[18];

    float *x, *bqkv;
    __half *h, *qkv, *vT, *attn, *ffn;
    __half *wqkvT, *woT, *w1T, *w2T;
    cudaGetSymbolAddress((void**)&x,    g_x);
    cudaGetSymbolAddress((void**)&h,    g_h);
    cudaGetSymbolAddress((void**)&qkv,  g_qkv);
    cudaGetSymbolAddress((void**)&vT,   g_vT);
    cudaGetSymbolAddress((void**)&attn, g_attn);
    cudaGetSymbolAddress((void**)&ffn,  g_ffn);
    cudaGetSymbolAddress((void**)&bqkv, g_bqkv);
    cudaGetSymbolAddress((void**)&wqkvT, g_wqkvT);
    cudaGetSymbolAddress((void**)&woT,  g_woT);
    cudaGetSymbolAddress((void**)&w1T,  g_w1T);
    cudaGetSymbolAddress((void**)&w2T,  g_w2T);

    const int SMG128 = (3 * 128 * PADH + 3 * 128 * PADH) * 2;  // 110592 B
    const int SMFL   = FQ_F * 2 + (128 * PSF + 3 * 128) * 4;   // 194048 B
    cudaFuncSetAttribute(mma_gemm<0,128>, cudaFuncAttributeMaxDynamicSharedMemorySize, SMG128);
    cudaFuncSetAttribute(mma_gemm<1,128>, cudaFuncAttributeMaxDynamicSharedMemorySize, SMG128);
    cudaFuncSetAttribute(mma_gemm<2,128>, cudaFuncAttributeMaxDynamicSharedMemorySize, SMG128);
    cudaFuncSetAttribute(flash_k, cudaFuncAttributeMaxDynamicSharedMemorySize, SMFL);

    cudaMemcpyAsync(x, src, sizeof(float) * (size_t)MTOT * EE, cudaMemcpyDeviceToDevice);

    // concat QKV bias
    for (int l = 0; l < LLAYERS; l++) {
        cudaMemcpyAsync(bqkv + l*QKVN,        bq + l*EE, EE*4, cudaMemcpyDeviceToDevice);
        cudaMemcpyAsync(bqkv + l*QKVN + EE,   bk + l*EE, EE*4, cudaMemcpyDeviceToDevice);
        cudaMemcpyAsync(bqkv + l*QKVN + 2*EE, bvv + l*EE, EE*4, cudaMemcpyDeviceToDevice);
    }

    // weight prep: Wq/Wk/Wv into concat wqkvT; others standalone
    dim3 tb(32, 8);
    const long long qkvLS = (long long)QKVN * EE;
    transpose_s<<<dim3(EE/32,  EE/32,  LLAYERS), tb>>>(Wq, wqkvT, EE, EE, qkvLS, 0);
    transpose_s<<<dim3(EE/32,  EE/32,  LLAYERS), tb>>>(Wk, wqkvT, EE, EE, qkvLS, EE);
    transpose_s<<<dim3(EE/32,  EE/32,  LLAYERS), tb>>>(Wv, wqkvT, EE, EE, qkvLS, 2*EE);
    transpose_s<<<dim3(EE/32,  EE/32,  LLAYERS), tb>>>(Wo, woT, EE, EE, (long long)EE*EE, 0);
    transpose_s<<<dim3(FFD/32, EE/32,  LLAYERS), tb>>>(W1, w1T, EE, FFD, (long long)FFD*EE, 0);
    transpose_s<<<dim3(EE/32,  FFD/32, LLAYERS), tb>>>(W2, w2T, FFD, EE, (long long)EE*FFD, 0);

    for (int l = 0; l < LLAYERS; ++l) {
        const __half* bwqkv = wqkvT + (size_t)l * QKVN * EE;
        const __half* bwo = woT + (size_t)l * EE * EE;
        const __half* bw1 = w1T + (size_t)l * FFD * EE;
        const __half* bw2 = w2T + (size_t)l * EE * FFD;

        ln_k<<<MTOT, 128>>>(x, ln1g + l * EE, ln1b + l * EE, h);

        // fused QKV projection: [8192,512] @ [1536,512]^T
        mma_gemm<0,128><<<dim3(QKVN/128, MTOT/128), 256, SMG128>>>(
            h, EE, bwqkv, EE, qkv, QKVLD, bqkv + l*QKVN, nullptr, MTOT, QKVN, EE);

        vtrans_k<<<dim3(DD/32, SS/32, BB*HH), tb>>>(qkv, vT);

        flash_k<<<dim3(SS/128, BB*HH), 256, SMFL>>>(qkv, vT, attn, edge, mask);

        // x = x + attn @ Wo + bo
        mma_gemm<2,128><<<dim3(EE/128, MTOT/128), 256, SMG128>>>(
            attn, EE, bwo, EE, x, EE, bo + l*EE, x, MTOT, EE, EE);

        ln_k<<<MTOT, 128>>>(x, ln2g + l * EE, ln2b + l * EE, h);

        mma_gemm<1,128><<<dim3(FFD/128, MTOT/128), 256, SMG128>>>(
            h, EE, bw1, EE, ffn, FFD, b1 + l*FFD, nullptr, MTOT, FFD, EE);

        mma_gemm<2,128><<<dim3(EE/128, MTOT/128), 256, SMG128>>>(
            ffn, FFD, bw2, FFD, x, EE, b2 + l*EE, x, MTOT, EE, FFD);
    }

    cudaMemcpyAsync(d_out, x, sizeof(float) * (size_t)MTOT * EE, cudaMemcpyDeviceToDevice);
}

// round 15
// speedup vs baseline: 1.0832x; 1.0832x over previous
#include <cuda_runtime.h>
#include <cuda_fp16.h>
#include <cstdint>
#include <math.h>
#include <float.h>

// Problem constants
#define BB  8
#define SS  1024
#define EE  512
#define HH  8
#define DD  64
#define FFD 2048
#define LLAYERS 4
#define MTOT (BB*SS)   // 8192 rows

// ---------------- scratch (static device globals; no allocations) -----------
__device__ float  g_x   [BB*SS*EE];          // residual stream (fp32)
__device__ __half g_h   [BB*SS*EE];
__device__ __half g_q   [BB*SS*EE];
__device__ __half g_k   [BB*SS*EE];
__device__ __half g_v   [BB*SS*EE];
__device__ __half g_vT  [BB*HH*DD*SS];
__device__ __half g_attn[BB*SS*EE];
__device__ __half g_ffn [BB*SS*FFD];
// transposed weights [N,K] K-major, fp16
__device__ __half g_wqT[LLAYERS*EE*EE];
__device__ __half g_wkT[LLAYERS*EE*EE];
__device__ __half g_wvT[LLAYERS*EE*EE];
__device__ __half g_woT[LLAYERS*EE*EE];
__device__ __half g_w1T[LLAYERS*FFD*EE];
__device__ __half g_w2T[LLAYERS*EE*FFD];

// ---------------- helpers ---------------------------------------------------
__device__ __forceinline__ uint32_t smem_u32(const void* p) {
    uint32_t a;
    asm("{ .reg .u64 t; cvta.to.shared.u64 t, %1; cvt.u32.u64 %0, t; }" : "=r"(a) : "l"(p));
    return a;
}
#define CP_ASYNC16(dst, src) \
    asm volatile("cp.async.ca.shared.global [%0], [%1], 16;" :: "r"(dst), "l"(src))
#define CP_COMMIT() asm volatile("cp.async.commit_group;" ::: "memory")
#define CP_WAIT1()  asm volatile("cp.async.wait_group 1;" ::: "memory")
#define CP_WAIT0()  asm volatile("cp.async.wait_group 0;" ::: "memory")
#define LDSM4(r0, r1, r2, r3, addr) \
    asm volatile("ldmatrix.sync.aligned.m8n8.x4.shared.b16 {%0,%1,%2,%3}, [%4];" \
        : "=r"(r0), "=r"(r1), "=r"(r2), "=r"(r3) : "r"(addr))
#define MMA_F16(acc, a, b) \
    asm volatile("mma.sync.aligned.m16n8k16.row.col.f32.f16.f16.f32 " \
        "{%0,%1,%2,%3}, {%4,%5,%6,%7}, {%8,%9}, {%0,%1,%2,%3};" \
        : "+f"((acc)[0]), "+f"((acc)[1]), "+f"((acc)[2]), "+f"((acc)[3]) \
        : "r"((a)[0]), "r"((a)[1]), "r"((a)[2]), "r"((a)[3]), "r"((b)[0]), "r"((b)[1]))

// ---------------- fp16 mma GEMM (R7 proven config: 2-stage, 2 syncs) ---------
// C[M,N] = epi( A[M,K] @ B[N,K]^T ).  BM=128, BN=128, BK=64 halves.
// 256 threads = 8 warps (4x2), warp tile 32x64.
// EPI: 0 +bias -> half out, 1 gelu(+bias) -> half out, 2 +bias+res -> float out
#define PADH 72
template<int EPI>
__global__ void __launch_bounds__(256)
mma_gemm(const __half* __restrict__ A, int lda,
         const __half* __restrict__ Bm, int ldb,
         void* __restrict__ Cv, int ldc,
         const float* __restrict__ bias, const float* __restrict__ res,
         int M, int N, int K)
{
    constexpr int BM = 128, BN = 128, NI = 8;

    extern __shared__ __half smh[];
    __half* Asm = smh;
    __half* Bsm = smh + 2 * BM * PADH;
    const uint32_t sbA = smem_u32(Asm), sbB = smem_u32(Bsm);

    const int tid = threadIdx.x, warp = tid >> 5, lane = tid & 31;
    const int g = lane >> 2, tg = lane & 3;
    const int wr = warp & 3, wc = warp >> 2;
    const int m0 = blockIdx.y * BM, n0 = blockIdx.x * BN;

    const int arow = wr * 32 + ((lane >> 3) & 1) * 8 + (lane & 7);
    const int acol = ((lane >> 4) & 1) * 8;
    const int brow = ((lane >> 4) & 1) * 8 + (lane & 7);
    const int bcol = ((lane >> 3) & 1) * 8;

    float acc[2][NI][4];
#pragma unroll
    for (int mi = 0; mi < 2; mi++)
#pragma unroll
        for (int ni = 0; ni < NI; ni++)
#pragma unroll
            for (int j = 0; j < 4; j++) acc[mi][ni][j] = 0.f;

    auto load_chunk = [&](int c, int buf) {
        const __half* Ab = A + (size_t)m0 * lda + c * 64;
#pragma unroll
        for (int i = 0; i < 4; i++) {
            int e = i * 256 + tid, row = e >> 3, c8 = e & 7;
            CP_ASYNC16(sbA + (uint32_t)(((buf * BM + row) * PADH + c8 * 8) * 2),
                       Ab + (size_t)row * lda + c8 * 8);
        }
        const __half* Bb = Bm + (size_t)n0 * ldb + c * 64;
#pragma unroll
        for (int i = 0; i < 4; i++) {
            int e = i * 256 + tid, row = e >> 3, c8 = e & 7;
            CP_ASYNC16(sbB + (uint32_t)(((buf * BN + row) * PADH + c8 * 8) * 2),
                       Bb + (size_t)row * ldb + c8 * 8);
        }
        CP_COMMIT();
    };

    auto compute = [&](int buf) {
        const uint32_t baA = sbA + (uint32_t)(buf * BM * PADH * 2);
        const uint32_t baB = sbB + (uint32_t)(buf * BN * PADH * 2);
#pragma unroll
        for (int ks = 0; ks < 4; ks++) {
            const int k0 = ks * 16;
            uint32_t af[2][4];
#pragma unroll
            for (int mi = 0; mi < 2; mi++)
                LDSM4(af[mi][0], af[mi][1], af[mi][2], af[mi][3],
                      baA + (uint32_t)(((arow + mi * 16) * PADH + k0 + acol) * 2));
            uint32_t bf[NI][2];
#pragma unroll
            for (int p = 0; p < 4; p++) {
                uint32_t r0, r1, r2, r3;
                LDSM4(r0, r1, r2, r3,
                      baB + (uint32_t)(((wc * 64 + brow + p * 16) * PADH + k0 + bcol) * 2));
                bf[2*p][0] = r0; bf[2*p][1] = r1;
                bf[2*p+1][0] = r2; bf[2*p+1][1] = r3;
            }
#pragma unroll
            for (int mi = 0; mi < 2; mi++)
#pragma unroll
                for (int ni = 0; ni < NI; ni++)
                    MMA_F16(acc[mi][ni], af[mi], bf[ni]);
        }
    };

    const int nch = K >> 6;
    load_chunk(0, 0);
    for (int c = 0; c < nch; ++c) {
        if (c + 1 < nch) { load_chunk(c + 1, (c + 1) & 1); CP_WAIT1(); }
        else             { CP_WAIT0(); }
        __syncthreads();
        compute(c & 1);
        __syncthreads();
    }

#pragma unroll
    for (int mi = 0; mi < 2; mi++)
#pragma unroll
        for (int ni = 0; ni < NI; ni++)
#pragma unroll
            for (int hh = 0; hh < 2; hh++) {
                const int r   = m0 + wr * 32 + mi * 16 + g + hh * 8;
                const int col = n0 + wc * 64 + ni * 8 + tg * 2;
                float vx = acc[mi][ni][hh * 2], vy = acc[mi][ni][hh * 2 + 1];
                float2 bb = *(const float2*)(bias + col);
                vx += bb.x; vy += bb.y;
                if (EPI == 1) {
                    vx = 0.5f * vx * (1.f + erff(vx * 0.70710678118654752f));
                    vy = 0.5f * vy * (1.f + erff(vy * 0.70710678118654752f));
                }
                if (EPI == 2) {
                    float2 rr = *(const float2*)(res + (size_t)r * ldc + col);
                    *(float2*)((float*)Cv + (size_t)r * ldc + col) =
                        make_float2(vx + rr.x, vy + rr.y);
                } else {
                    *(__half2*)((__half*)Cv + (size_t)r * ldc + col) =
                        __floats2half2_rn(vx, vy);
                }
            }
}

// ---------------- fused flash attention (R7 design + K/V double buffer) ------
#define PVH 136   // V/P row stride in halves
#define PSF 132   // S row stride in floats
// smem layout in halves:
#define FQ_K  (128*PADH)                  // after Q: 2 K buffers
#define FQ_V  (FQ_K + 2*128*PADH)         // 2 V buffers
#define FQ_P  (FQ_V + 2*64*PVH)           // P (fp16)
#define FQ_F  (FQ_P + 128*PVH)            // float region start (in halves)
__global__ void __launch_bounds__(256)
flash_k(const __half* __restrict__ q, const __half* __restrict__ kg,
        const __half* __restrict__ vt, __half* __restrict__ o,
        const float* __restrict__ edge, const unsigned char* __restrict__ mask)
{
    extern __shared__ __half smh[];
    float* Ssm  = (float*)(smh + FQ_F);   // 128*132
    float* mrow = Ssm + 128 * PSF;
    float* lrow = mrow + 128;
    float* rowf = lrow + 128;

    const int tid = threadIdx.x, warp = tid >> 5, lane = tid & 31;
    const int g = lane >> 2, tg = lane & 3;
    const int wr = warp & 3, wc = warp >> 2;
    const int t0 = blockIdx.x * 128;
    const int bh = blockIdx.y, b = bh >> 3, h = bh & 7;

    const __half* Qg = q  + ((size_t)b * SS + t0) * EE + h * DD;
    const __half* Kg = kg + (size_t)b * SS * EE + h * DD;
    const __half* Vg = vt + (size_t)bh * DD * SS;
    const uint32_t sQ = smem_u32(smh);
    const uint32_t sP = sQ + (uint32_t)(FQ_P * 2);

    // Q tile (128 x 64 halves)
#pragma unroll
    for (int i = 0; i < 4; i++) {
        int e = i * 256 + tid, row = e >> 3, c8 = e & 7;
        CP_ASYNC16(sQ + (uint32_t)((row * PADH + c8 * 8) * 2), Qg + (size_t)row * EE + c8 * 8);
    }
    CP_COMMIT();

    auto load_kv = [&](int kt, int buf) {
        const int s0 = kt * 128;
        const uint32_t sK = sQ + (uint32_t)((FQ_K + buf * 128 * PADH) * 2);
        const uint32_t sV = sQ + (uint32_t)((FQ_V + buf * 64 * PVH) * 2);
#pragma unroll
        for (int i = 0; i < 4; i++) {
            int e = i * 256 + tid, row = e >> 3, c8 = e & 7;
            CP_ASYNC16(sK + (uint32_t)((row * PADH + c8 * 8) * 2),
                       Kg + (size_t)(s0 + row) * EE + c8 * 8);
        }
#pragma unroll
        for (int i = 0; i < 4; i++) {
            int e = i * 256 + tid, row = e >> 4, c8 = e & 15;
            CP_ASYNC16(sV + (uint32_t)((row * PVH + c8 * 8) * 2),
                       Vg + (size_t)row * SS + s0 + c8 * 8);
        }
        CP_COMMIT();
    };
    load_kv(0, 0);

    if (tid < 128) { mrow[tid] = -FLT_MAX; lrow[tid] = 0.f; }

    float acco[2][4][4];
#pragma unroll
    for (int mi = 0; mi < 2; mi++)
#pragma unroll
        for (int ni = 0; ni < 4; ni++)
#pragma unroll
            for (int j = 0; j < 4; j++) acco[mi][ni][j] = 0.f;

    const int arow = wr * 32 + ((lane >> 3) & 1) * 8 + (lane & 7);
    const int acol = ((lane >> 4) & 1) * 8;
    const int brow = ((lane >> 4) & 1) * 8 + (lane & 7);
    const int bcol = ((lane >> 3) & 1) * 8;

    for (int kt = 0; kt < 8; kt++) {
        const int s0 = kt * 128;
        const int buf = kt & 1;
        if (kt < 7) { load_kv(kt + 1, buf ^ 1); CP_WAIT1(); }
        else        { CP_WAIT0(); }
        __syncthreads();
        const uint32_t sK = sQ + (uint32_t)((FQ_K + buf * 128 * PADH) * 2);
        const uint32_t sV = sQ + (uint32_t)((FQ_V + buf * 64 * PVH) * 2);

        // S = Q @ K^T (128x128), warp tile 32x64, k=64 -> 4 k16 steps
        float accs[2][8][4];
#pragma unroll
        for (int mi = 0; mi < 2; mi++)
#pragma unroll
            for (int ni = 0; ni < 8; ni++)
#pragma unroll
                for (int j = 0; j < 4; j++) accs[mi][ni][j] = 0.f;
#pragma unroll
        for (int ks = 0; ks < 4; ks++) {
            const int k0 = ks * 16;
            uint32_t af[2][4];
#pragma unroll
            for (int mi = 0; mi < 2; mi++)
                LDSM4(af[mi][0], af[mi][1], af[mi][2], af[mi][3],
                      sQ + (uint32_t)(((arow + mi * 16) * PADH + k0 + acol) * 2));
            uint32_t bf[8][2];
#pragma unroll
            for (int p = 0; p < 4; p++) {
                uint32_t r0, r1, r2, r3;
                LDSM4(r0, r1, r2, r3,
                      sK + (uint32_t)(((wc * 64 + brow + p * 16) * PADH + k0 + bcol) * 2));
                bf[2*p][0] = r0; bf[2*p][1] = r1;
                bf[2*p+1][0] = r2; bf[2*p+1][1] = r3;
            }
#pragma unroll
            for (int mi = 0; mi < 2; mi++)
#pragma unroll
                for (int ni = 0; ni < 8; ni++)
                    MMA_F16(accs[mi][ni], af[mi], bf[ni]);
        }

        // scale + mask + edge -> Ssm (fp32)
#pragma unroll
        for (int mi = 0; mi < 2; mi++)
#pragma unroll
            for (int ni = 0; ni < 8; ni++)
#pragma unroll
                for (int hh = 0; hh < 2; hh++) {
                    const int r  = wr * 32 + mi * 16 + g + hh * 8;
                    const int cc = wc * 64 + ni * 8 + tg * 2;
                    float2 ee = *(const float2*)(edge + ((size_t)b * SS + t0 + r) * SS + s0 + cc);
                    const unsigned char* Mp = mask + (size_t)b * SS + s0 + cc;
                    Ssm[r * PSF + cc]     = (Mp[0] ? -FLT_MAX : accs[mi][ni][hh*2]     * 0.125f) + ee.x;
                    Ssm[r * PSF + cc + 1] = (Mp[1] ? -FLT_MAX : accs[mi][ni][hh*2 + 1] * 0.125f) + ee.y;
                }
        __syncthreads();

        // online softmax: 2 threads per row, 64 cols each; write P as fp16
        {
            const int r = tid >> 1, hf = tid & 1;
            const float* Sr = Ssm + r * PSF + hf * 64;
            __half* Pr = (__half*)(smh + FQ_P) + r * PVH + hf * 64;
            float mloc = -FLT_MAX;
#pragma unroll
            for (int j = 0; j < 64; j += 4) {
                float4 v4 = *(const float4*)(Sr + j);
                mloc = fmaxf(mloc, fmaxf(fmaxf(v4.x, v4.y), fmaxf(v4.z, v4.w)));
            }
            mloc = fmaxf(mloc, __shfl_xor_sync(0xffffffffu, mloc, 1));
            const float mold = mrow[r];
            const float mnew = fmaxf(mold, mloc);
            const float f = __expf(mold - mnew);
            float sum = 0.f;
#pragma unroll
            for (int j = 0; j < 64; j += 4) {
                float4 v4 = *(const float4*)(Sr + j);
                v4.x = __expf(v4.x - mnew); v4.y = __expf(v4.y - mnew);
                v4.z = __expf(v4.z - mnew); v4.w = __expf(v4.w - mnew);
                sum += v4.x + v4.y + v4.z + v4.w;
                *(__half2*)(Pr + j)     = __floats2half2_rn(v4.x, v4.y);
                *(__half2*)(Pr + j + 2) = __floats2half2_rn(v4.z, v4.w);
            }
            sum += __shfl_xor_sync(0xffffffffu, sum, 1);
            if (hf == 0) { mrow[r] = mnew; rowf[r] = f; lrow[r] = lrow[r] * f + sum; }
        }
        __syncthreads();

        // rescale O accumulators
#pragma unroll
        for (int mi = 0; mi < 2; mi++)
#pragma unroll
            for (int hh = 0; hh < 2; hh++) {
                const int r = wr * 32 + mi * 16 + g + hh * 8;
                const float f = rowf[r];
#pragma unroll
                for (int ni = 0; ni < 4; ni++) {
                    acco[mi][ni][hh*2]     *= f;
                    acco[mi][ni][hh*2 + 1] *= f;
                }
            }

        // O += P @ V : warp tile 32x32, 8 k16 steps
#pragma unroll
        for (int ks = 0; ks < 8; ks++) {
            const int k0 = ks * 16;
            uint32_t af[2][4];
#pragma unroll
            for (int mi = 0; mi < 2; mi++)
                LDSM4(af[mi][0], af[mi][1], af[mi][2], af[mi][3],
                      sP + (uint32_t)(((arow + mi * 16) * PVH + k0 + acol) * 2));
            uint32_t bf[4][2];
#pragma unroll
            for (int p = 0; p < 2; p++) {
                uint32_t r0, r1, r2, r3;
                LDSM4(r0, r1, r2, r3,
                      sV + (uint32_t)(((wc * 32 + brow + p * 16) * PVH + k0 + bcol) * 2));
                bf[2*p][0] = r0; bf[2*p][1] = r1;
                bf[2*p+1][0] = r2; bf[2*p+1][1] = r3;
            }
#pragma unroll
            for (int mi = 0; mi < 2; mi++)
#pragma unroll
                for (int ni = 0; ni < 4; ni++)
                    MMA_F16(acco[mi][ni], af[mi], bf[ni]);
        }
        __syncthreads();   // protect P buffer + mrow/lrow for next iteration
    }

    // write O = acc / l  (fp16, feeds Wo GEMM)
#pragma unroll
    for (int mi = 0; mi < 2; mi++)
#pragma unroll
        for (int ni = 0; ni < 4; ni++)
#pragma unroll
            for (int hh = 0; hh < 2; hh++) {
                const int r = wr * 32 + mi * 16 + g + hh * 8;
                const int d = wc * 32 + ni * 8 + tg * 2;
                const float inv = 1.f / lrow[r];
                *(__half2*)(o + ((size_t)b * SS + t0 + r) * EE + h * DD + d) =
                    __floats2half2_rn(acco[mi][ni][hh*2] * inv, acco[mi][ni][hh*2+1] * inv);
            }
}

// ---------------- weight transpose fp32 -> fp16 ------------------------------
__global__ void transpose_s(const float* __restrict__ in, __half* __restrict__ out,
                            int R, int Ccols)
{
    in  += (size_t)blockIdx.z * R * Ccols;
    out += (size_t)blockIdx.z * R * Ccols;
    __shared__ float t[32][33];
    const int c0 = blockIdx.x * 32, r0 = blockIdx.y * 32;
    const int x = threadIdx.x, y = threadIdx.y;
#pragma unroll
    for (int i = 0; i < 32; i += 8)
        t[y + i][x] = in[(size_t)(r0 + y + i) * Ccols + c0 + x];
    __syncthreads();
#pragma unroll
    for (int i = 0; i < 32; i += 8)
        out[(size_t)(c0 + y + i) * R + r0 + x] = __float2half_rn(t[x][y + i]);
}

// ---------------- V transpose (half -> half) ---------------------------------
__global__ void vtrans_k(const __half* __restrict__ v, __half* __restrict__ vT)
{
    const int z = blockIdx.z, b = z >> 3, h = z & 7;
    const __half* in = v + (size_t)b * SS * EE + h * DD;
    __half* out = vT + (size_t)z * DD * SS;
    __shared__ __half t[32][36];
    const int d0 = blockIdx.x * 32, s0 = blockIdx.y * 32;
    const int x = threadIdx.x, y = threadIdx.y;
#pragma unroll
    for (int i = 0; i < 32; i += 8)
        t[y + i][x] = in[(size_t)(s0 + y + i) * EE + d0 + x];
    __syncthreads();
#pragma unroll
    for (int i = 0; i < 32; i += 8)
        out[(size_t)(d0 + y + i) * SS + s0 + x] = t[x][y + i];
}

// ---------------- layernorm (fp32 in -> fp16 out) ----------------------------
__global__ __launch_bounds__(128)
void ln_k(const float* __restrict__ x, const float* __restrict__ g,
          const float* __restrict__ b, __half* __restrict__ o)
{
    const size_t row = blockIdx.x;
    const int tid = threadIdx.x;
    __shared__ float sma[4], smb[4];

    float4 v = ((const float4*)(x + row * EE))[tid];
    float s = v.x + v.y + v.z + v.w;
#pragma unroll
    for (int off = 16; off > 0; off >>= 1) s += __shfl_xor_sync(0xffffffffu, s, off);
    if ((tid & 31) == 0) sma[tid >> 5] = s;
    __syncthreads();
    const float mu = (sma[0] + sma[1] + sma[2] + sma[3]) * (1.f / EE);

    float4 d = make_float4(v.x - mu, v.y - mu, v.z - mu, v.w - mu);
    float s2 = d.x*d.x + d.y*d.y + d.z*d.z + d.w*d.w;
#pragma unroll
    for (int off = 16; off > 0; off >>= 1) s2 += __shfl_xor_sync(0xffffffffu, s2, off);
    if ((tid & 31) == 0) smb[tid >> 5] = s2;
    __syncthreads();
    const float var = (smb[0] + smb[1] + smb[2] + smb[3]) * (1.f / EE);
    const float rstd = rsqrtf(var + 1e-5f);

    float4 gg = ((const float4*)g)[tid];
    float4 bb = ((const float4*)b)[tid];
    __half2* op = (__half2*)(o + row * EE);
    op[tid * 2]     = __floats2half2_rn(d.x*rstd*gg.x + bb.x, d.y*rstd*gg.y + bb.y);
    op[tid * 2 + 1] = __floats2half2_rn(d.z*rstd*gg.z + bb.z, d.w*rstd*gg.w + bb.w);
}

// ---------------- host orchestration ----------------------------------------
extern "C" void kernel_launch(void* const* d_in, const int* in_sizes, int n_in,
                              void* d_out, int out_size)
{
    const float* src  = (const float*)d_in[0];
    const float* edge = (const float*)d_in[1];
    const unsigned char* mask = (const unsigned char*)d_in[2];
    const float* Wq = (const float*)d_in[3];
    const float* bq = (const float*)d_in[4];
    const float* Wk = (const float*)d_in[5];
    const float* bk = (const float*)d_in[6];
    const float* Wv = (const float*)d_in[7];
    const float* bvv = (const float*)d_in[8];
    const float* Wo = (const float*)d_in[9];
    const float* bo = (const float*)d_in[10];
    const float* ln1g = (const float*)d_in[11];
    const float* ln1b = (const float*)d_in[12];
    const float* ln2g = (const float*)d_in[13];
    const float* ln2b = (const float*)d_in[14];
    const float* W1 = (const float*)d_in[15];
    const float* b1 = (const float*)d_in[16];
    const float* W2 = (const float*)d_in[17];
    const float* b2 = (const float*)d_in[18];

    float *x;
    __half *h, *q, *kk, *vv, *vT, *attn, *ffn;
    __half *wqT, *wkT, *wvT, *woT, *w1T, *w2T;
    cudaGetSymbolAddress((void**)&x,    g_x);
    cudaGetSymbolAddress((void**)&h,    g_h);
    cudaGetSymbolAddress((void**)&q,    g_q);
    cudaGetSymbolAddress((void**)&kk,   g_k);
    cudaGetSymbolAddress((void**)&vv,   g_v);
    cudaGetSymbolAddress((void**)&vT,   g_vT);
    cudaGetSymbolAddress((void**)&attn, g_attn);
    cudaGetSymbolAddress((void**)&ffn,  g_ffn);
    cudaGetSymbolAddress((void**)&wqT,  g_wqT);
    cudaGetSymbolAddress((void**)&wkT,  g_wkT);
    cudaGetSymbolAddress((void**)&wvT,  g_wvT);
    cudaGetSymbolAddress((void**)&woT,  g_woT);
    cudaGetSymbolAddress((void**)&w1T,  g_w1T);
    cudaGetSymbolAddress((void**)&w2T,  g_w2T);

    const int SMG  = (2 * 128 * PADH + 2 * 128 * PADH) * 2;    // 73728 B (2 CTAs/SM)
    const int SMFL = FQ_F * 2 + (128 * PSF + 3 * 128) * 4;     // 194048 B (1 CTA/SM)
    cudaFuncSetAttribute(mma_gemm<0>, cudaFuncAttributeMaxDynamicSharedMemorySize, SMG);
    cudaFuncSetAttribute(mma_gemm<1>, cudaFuncAttributeMaxDynamicSharedMemorySize, SMG);
    cudaFuncSetAttribute(mma_gemm<2>, cudaFuncAttributeMaxDynamicSharedMemorySize, SMG);
    cudaFuncSetAttribute(flash_k, cudaFuncAttributeMaxDynamicSharedMemorySize, SMFL);

    cudaMemcpyAsync(x, src, sizeof(float) * (size_t)MTOT * EE, cudaMemcpyDeviceToDevice);

    // Pre-transpose + fp16-convert all weights (batched over layers)
    dim3 tb(32, 8);
    transpose_s<<<dim3(EE/32,  EE/32,  LLAYERS), tb>>>(Wq, wqT, EE, EE);
    transpose_s<<<dim3(EE/32,  EE/32,  LLAYERS), tb>>>(Wk, wkT, EE, EE);
    transpose_s<<<dim3(EE/32,  EE/32,  LLAYERS), tb>>>(Wv, wvT, EE, EE);
    transpose_s<<<dim3(EE/32,  EE/32,  LLAYERS), tb>>>(Wo, woT, EE, EE);
    transpose_s<<<dim3(FFD/32, EE/32,  LLAYERS), tb>>>(W1, w1T, EE, FFD);
    transpose_s<<<dim3(EE/32,  FFD/32, LLAYERS), tb>>>(W2, w2T, FFD, EE);

    for (int l = 0; l < LLAYERS; ++l) {
        const __half* bwq = wqT + (size_t)l * EE * EE;
        const __half* bwk = wkT + (size_t)l * EE * EE;
        const __half* bwv = wvT + (size_t)l * EE * EE;
        const __half* bwo = woT + (size_t)l * EE * EE;
        const __half* bw1 = w1T + (size_t)l * FFD * EE;
        const __half* bw2 = w2T + (size_t)l * EE * FFD;

        ln_k<<<MTOT, 128>>>(x, ln1g + l * EE, ln1b + l * EE, h);

        dim3 gP(EE / 128, MTOT / 128, 1);
        mma_gemm<0><<<gP, 256, SMG>>>(h, EE, bwq, EE, q,  EE, bq + l*EE, nullptr, MTOT, EE, EE);
        mma_gemm<0><<<gP, 256, SMG>>>(h, EE, bwk, EE, kk, EE, bk + l*EE, nullptr, MTOT, EE, EE);
        mma_gemm<0><<<gP, 256, SMG>>>(h, EE, bwv, EE, vv, EE, bvv + l*EE, nullptr, MTOT, EE, EE);

        vtrans_k<<<dim3(DD/32, SS/32, BB*HH), tb>>>(vv, vT);

        // fused attention (double-buffered K/V)
        flash_k<<<dim3(SS/128, BB*HH), 256, SMFL>>>(q, kk, vT, attn, edge, mask);

        // x = x + attn @ Wo + bo
        mma_gemm<2><<<gP, 256, SMG>>>(attn, EE, bwo, EE, x, EE, bo + l*EE, x, MTOT, EE, EE);

        ln_k<<<MTOT, 128>>>(x, ln2g + l * EE, ln2b + l * EE, h);

        // FFN1 + exact GELU
        dim3 gF(FFD / 128, MTOT / 128, 1);
        mma_gemm<1><<<gF, 256, SMG>>>(h, EE, bw1, EE, ffn, FFD, b1 + l*FFD, nullptr, MTOT, FFD, EE);

        // FFN2 + residual
        mma_gemm<2><<<gP, 256, SMG>>>(ffn, FFD, bw2, FFD, x, EE, b2 + l*EE, x, MTOT, EE, FFD);
    }

    cudaMemcpyAsync(d_out, x, sizeof(float) * (size_t)MTOT * EE, cudaMemcpyDeviceToDevice);
}